// round 8
// baseline (speedup 1.0000x reference)
#include <cuda_runtime.h>
#include <math.h>

// Problem constants
#define Bb 256
#define Tt 512
#define Ii 64
#define Hh 128
#define GH 512          // 4*H
#define NB 4            // batch samples per recurrence CTA
#define KS 96           // weight cols kept in smem (cols 96..127 live in regs)
#define WSTR 100        // padded smem row stride (words): 25 quads -> conflict-free LDS.128

typedef unsigned long long ull;

// permutation: gate row n -> slot p(n) so that quad lanes own rows {j,j+128,j+256,j+384}
#define PSLOT(n) ((((n) & 127) << 2) | ((n) >> 7))

// ---------------- scratch (device globals; no cudaMalloc allowed) ----------
__device__ float g_xg[2 * Bb * Tt * GH];     // [dir][b][t][4H]  (PERMUTED in last dim)
__device__ float g_h0[Bb * Tt * 2 * Hh];     // layer0 output [b][t][2H]
__device__ float g_h1[Bb * Tt * 2 * Hh];     // layer1 output [b][t][2H]

// ---------------- f32x2 helpers (packed fp32 FMA, sm_100+) -----------------
__device__ __forceinline__ ull pk2(float x, float y) {
    ull r; asm("mov.b64 %0, {%1, %2};" : "=l"(r) : "f"(x), "f"(y)); return r;
}
__device__ __forceinline__ void fma2(ull& d, ull a, ull b) {
    asm("fma.rn.f32x2 %0, %1, %2, %0;" : "+l"(d) : "l"(a), "l"(b));
}
__device__ __forceinline__ void unpk2(ull v, float& x, float& y) {
    asm("mov.b64 {%0, %1}, %2;" : "=f"(x), "=f"(y) : "l"(v));
}
__device__ __forceinline__ float f4c(const float4 v, int i) {
    return i == 0 ? v.x : i == 1 ? v.y : i == 2 ? v.z : v.w;
}
// fast activations: __expf + MUFU.RCP; proven rel err ~3.6e-7 end-to-end
__device__ __forceinline__ float sigf(float x) {
    float e = __expf(-x);
    return __fdividef(1.0f, 1.0f + e);
}
__device__ __forceinline__ float tanhfast(float x) {
    float e = __expf(-2.0f * x);
    return __fdividef(1.0f - e, 1.0f + e);
}

// ---------------- xg GEMM v2: Y[dir][m][p(n)] = X[m,:]·W[n,:] + bih+bhh ----
// CTA tile 128m x 128n, BK=16, 256 threads, thread tile 8x8 (4+4 split).
// Double-buffered smem; epilogue stores PERMUTED (slot p(n)).
__global__ void __launch_bounds__(256) xg_gemm(
    const float* __restrict__ X0, int layer, int K,
    const float* __restrict__ W0, const float* __restrict__ W1,
    const float* __restrict__ bi0, const float* __restrict__ bh0,
    const float* __restrict__ bi1, const float* __restrict__ bh1)
{
    const int M = Bb * Tt;
    __shared__ float Xs[2][16][132];
    __shared__ float Ws[2][16][132];
    const float* X  = layer ? g_h0 : X0;
    const int dir   = blockIdx.z;
    const float* W  = dir ? W1 : W0;
    const float* bi = dir ? bi1 : bi0;
    const float* bh = dir ? bh1 : bh0;
    const int m0 = blockIdx.x * 128;
    const int n0 = blockIdx.y * 128;
    const int tid = threadIdx.x;
    const int tx = tid & 15, ty = tid >> 4;
    const int gr = tid & 127, qh = tid >> 7;   // global-load row, k-half

    const float* Xp = X + (size_t)(m0 + gr) * K + 8 * qh;
    const float* Wp = W + (size_t)(n0 + gr) * K + 8 * qh;

    float4 xr0 = *(const float4*)Xp, xr1 = *(const float4*)(Xp + 4);
    float4 wr0 = *(const float4*)Wp, wr1 = *(const float4*)(Wp + 4);
    const int kq = 8 * qh;
    Xs[0][kq+0][gr]=xr0.x; Xs[0][kq+1][gr]=xr0.y; Xs[0][kq+2][gr]=xr0.z; Xs[0][kq+3][gr]=xr0.w;
    Xs[0][kq+4][gr]=xr1.x; Xs[0][kq+5][gr]=xr1.y; Xs[0][kq+6][gr]=xr1.z; Xs[0][kq+7][gr]=xr1.w;
    Ws[0][kq+0][gr]=wr0.x; Ws[0][kq+1][gr]=wr0.y; Ws[0][kq+2][gr]=wr0.z; Ws[0][kq+3][gr]=wr0.w;
    Ws[0][kq+4][gr]=wr1.x; Ws[0][kq+5][gr]=wr1.y; Ws[0][kq+6][gr]=wr1.z; Ws[0][kq+7][gr]=wr1.w;
    __syncthreads();

    ull acc[8][4];
#pragma unroll
    for (int i = 0; i < 8; i++)
#pragma unroll
        for (int j = 0; j < 4; j++) acc[i][j] = 0ull;

    const int NIT = K / 16;
    for (int it = 0; it < NIT; ++it) {
        const int cur = it & 1;
        if (it + 1 < NIT) {
            const float* xp = Xp + (it + 1) * 16;
            const float* wp = Wp + (it + 1) * 16;
            xr0 = *(const float4*)xp; xr1 = *(const float4*)(xp + 4);
            wr0 = *(const float4*)wp; wr1 = *(const float4*)(wp + 4);
        }
#pragma unroll
        for (int k = 0; k < 16; ++k) {
            float4 xa = *(const float4*)&Xs[cur][k][ty * 4];
            float4 xb = *(const float4*)&Xs[cur][k][64 + ty * 4];
            float4 wa = *(const float4*)&Ws[cur][k][tx * 4];
            float4 wb = *(const float4*)&Ws[cur][k][64 + tx * 4];
            ull p0 = pk2(wa.x, wa.y), p1 = pk2(wa.z, wa.w);
            ull p2 = pk2(wb.x, wb.y), p3 = pk2(wb.z, wb.w);
            ull a;
            a = pk2(xa.x, xa.x);
            fma2(acc[0][0],a,p0); fma2(acc[0][1],a,p1); fma2(acc[0][2],a,p2); fma2(acc[0][3],a,p3);
            a = pk2(xa.y, xa.y);
            fma2(acc[1][0],a,p0); fma2(acc[1][1],a,p1); fma2(acc[1][2],a,p2); fma2(acc[1][3],a,p3);
            a = pk2(xa.z, xa.z);
            fma2(acc[2][0],a,p0); fma2(acc[2][1],a,p1); fma2(acc[2][2],a,p2); fma2(acc[2][3],a,p3);
            a = pk2(xa.w, xa.w);
            fma2(acc[3][0],a,p0); fma2(acc[3][1],a,p1); fma2(acc[3][2],a,p2); fma2(acc[3][3],a,p3);
            a = pk2(xb.x, xb.x);
            fma2(acc[4][0],a,p0); fma2(acc[4][1],a,p1); fma2(acc[4][2],a,p2); fma2(acc[4][3],a,p3);
            a = pk2(xb.y, xb.y);
            fma2(acc[5][0],a,p0); fma2(acc[5][1],a,p1); fma2(acc[5][2],a,p2); fma2(acc[5][3],a,p3);
            a = pk2(xb.z, xb.z);
            fma2(acc[6][0],a,p0); fma2(acc[6][1],a,p1); fma2(acc[6][2],a,p2); fma2(acc[6][3],a,p3);
            a = pk2(xb.w, xb.w);
            fma2(acc[7][0],a,p0); fma2(acc[7][1],a,p1); fma2(acc[7][2],a,p2); fma2(acc[7][3],a,p3);
        }
        if (it + 1 < NIT) {
            const int nxt = cur ^ 1;
            Xs[nxt][kq+0][gr]=xr0.x; Xs[nxt][kq+1][gr]=xr0.y; Xs[nxt][kq+2][gr]=xr0.z; Xs[nxt][kq+3][gr]=xr0.w;
            Xs[nxt][kq+4][gr]=xr1.x; Xs[nxt][kq+5][gr]=xr1.y; Xs[nxt][kq+6][gr]=xr1.z; Xs[nxt][kq+7][gr]=xr1.w;
            Ws[nxt][kq+0][gr]=wr0.x; Ws[nxt][kq+1][gr]=wr0.y; Ws[nxt][kq+2][gr]=wr0.z; Ws[nxt][kq+3][gr]=wr0.w;
            Ws[nxt][kq+4][gr]=wr1.x; Ws[nxt][kq+5][gr]=wr1.y; Ws[nxt][kq+6][gr]=wr1.z; Ws[nxt][kq+7][gr]=wr1.w;
        }
        __syncthreads();
    }

    const int na = n0 + tx * 4, nb = na + 64;
    float bsA[4], bsB[4];
#pragma unroll
    for (int j = 0; j < 4; j++) {
        bsA[j] = bi[na + j] + bh[na + j];
        bsB[j] = bi[nb + j] + bh[nb + j];
    }
    float* base = g_xg + (size_t)dir * M * GH;
#pragma unroll
    for (int i = 0; i < 8; ++i) {
        const int m = m0 + (i < 4 ? ty * 4 + i : 64 + ty * 4 + (i - 4));
        float* y = base + (size_t)m * GH;
        float v0, v1, v2, v3;
        unpk2(acc[i][0], v0, v1); unpk2(acc[i][1], v2, v3);
        y[PSLOT(na)]     = v0 + bsA[0];
        y[PSLOT(na + 1)] = v1 + bsA[1];
        y[PSLOT(na + 2)] = v2 + bsA[2];
        y[PSLOT(na + 3)] = v3 + bsA[3];
        unpk2(acc[i][2], v0, v1); unpk2(acc[i][3], v2, v3);
        y[PSLOT(nb)]     = v0 + bsB[0];
        y[PSLOT(nb + 1)] = v1 + bsB[1];
        y[PSLOT(nb + 2)] = v2 + bsB[2];
        y[PSLOT(nb + 3)] = v3 + bsB[3];
    }
}

// ---------------- LSTM recurrence: one CTA = (direction, 4 batch samples) --
// 512 threads. Thread tid owns gate row r = (tid&3)*128 + (tid>>2) (slot tid)
// for all NB batches. One barrier per step: gate exchange done with 3
// shfl.xor within the lane quad; hs ping-pongs (WAR safety).
__global__ void __launch_bounds__(512, 1) lstm_rec(
    int layer,
    const float* __restrict__ Wf, const float* __restrict__ Wr)
{
    extern __shared__ float sm[];
    float* sW  = sm;                       // 512 * WSTR floats (permuted slots)
    float* hsA = sm + GH * WSTR;           // ping [128][NB]
    float* hsB = hsA + NB * Hh;            // pong [128][NB]

    const int dir = blockIdx.y;
    const int b0  = blockIdx.x * NB;
    const float* Whh = dir ? Wr : Wf;
    float* hout = layer ? g_h1 : g_h0;
    const float* xg = g_xg + (size_t)dir * Bb * Tt * GH;
    const int tid  = threadIdx.x;
    const int lane = tid & 31, wid = tid >> 5;

    // weights: cols [0,96) of every row into smem at PERMUTED slot
    {
        const float4* src = (const float4*)Whh;   // 32 float4 per row
        for (int r = wid; r < GH; r += 16) {
            const int ps = PSLOT(r);
            if (lane < 24)
                *(float4*)(sW + ps * WSTR + lane * 4) = src[r * 32 + lane];
        }
        for (int i = tid; i < 2 * NB * Hh; i += 512) hsA[i] = 0.f;
    }
    // this thread's row: cols [96,128) in registers
    const int rthr = ((tid & 3) << 7) | (tid >> 2);
    float4 wreg[8];
    {
        const float4* src = (const float4*)(Whh + (size_t)rthr * Hh);
#pragma unroll
        for (int j = 0; j < 8; ++j) wreg[j] = src[24 + j];
    }
    const int e = tid & 3;                // gate type AND owned batch
    const int q = tid >> 2;               // hidden index j
    const bool p0 = (e & 1) != 0, p1 = (e & 2) != 0;
    float c0 = 0.f;
    const float* wrow = sW + tid * WSTR;
    float* hp = hout + (size_t)(b0 + e) * Tt * (2 * Hh) + dir * Hh + q;
    __syncthreads();

    const size_t TG = (size_t)Tt * GH;
    for (int s = 0; s < Tt; ++s) {
        const int t = dir ? (Tt - 1 - s) : s;
        const float* hcur = (s & 1) ? hsB : hsA;
        float* hnxt       = (s & 1) ? hsA : hsB;
        const size_t xb = (size_t)b0 * TG + (size_t)t * GH + tid;
        // prefetch xg (permuted layout -> coalesced), consumed post-GEMM
        float x0 = xg[xb];
        float x1 = xg[xb + TG];
        float x2 = xg[xb + 2 * TG];
        float x3 = xg[xb + 3 * TG];

        ull a01 = 0, a23 = 0;
#pragma unroll 6
        for (int k = 0; k < KS; k += 4) {
            float4 wv = *(const float4*)(wrow + k);
#pragma unroll
            for (int kk = 0; kk < 4; ++kk) {
                float4 hv = *(const float4*)(hcur + 4 * (k + kk));
                ull h01 = pk2(hv.x, hv.y), h23 = pk2(hv.z, hv.w);
                float w1 = f4c(wv, kk);
                ull am = pk2(w1, w1);
                fma2(a01, am, h01); fma2(a23, am, h23);
            }
        }
#pragma unroll
        for (int j = 0; j < 8; ++j) {
            float4 wv = wreg[j];
            const int k = KS + 4 * j;
#pragma unroll
            for (int kk = 0; kk < 4; ++kk) {
                float4 hv = *(const float4*)(hcur + 4 * (k + kk));
                ull h01 = pk2(hv.x, hv.y), h23 = pk2(hv.z, hv.w);
                float w1 = f4c(wv, kk);
                ull am = pk2(w1, w1);
                fma2(a01, am, h01); fma2(a23, am, h23);
            }
        }

        float a0, a1, a2, a3;
        unpk2(a01, a0, a1); unpk2(a23, a2, a3);
        a0 += x0; a1 += x1; a2 += x2; a3 += x3;   // preact: gate e, batches 0..3

        // 4x4 quad transpose: thread ends with gates 0..3 for batch e.
        // round r: send a[e^r], recv from lane^r => gate (e^r) of batch e.
        float own = p1 ? (p0 ? a3 : a2) : (p0 ? a1 : a0);   // a[e]
        float s1  = p1 ? (p0 ? a2 : a3) : (p0 ? a0 : a1);   // a[e^1]
        float s2  = p1 ? (p0 ? a1 : a0) : (p0 ? a3 : a2);   // a[e^2]
        float s3  = p1 ? (p0 ? a0 : a1) : (p0 ? a2 : a3);   // a[e^3]
        float v1 = __shfl_xor_sync(0xffffffffu, s1, 1);
        float v2 = __shfl_xor_sync(0xffffffffu, s2, 2);
        float v3 = __shfl_xor_sync(0xffffffffu, s3, 3);
        // G_i = v[e^i] with v[] = {own, v1, v2, v3}
        float G0 = p1 ? (p0 ? v3 : v2) : (p0 ? v1 : own);
        float G1 = p1 ? (p0 ? v2 : v3) : (p0 ? own : v1);
        float G2 = p1 ? (p0 ? v1 : own) : (p0 ? v3 : v2);
        float G3 = p1 ? (p0 ? own : v1) : (p0 ? v2 : v3);

        // elementwise: this thread owns (batch e, hidden q)
        c0 = sigf(G1) * c0 + sigf(G0) * tanhfast(G2);
        float h = sigf(G3) * tanhfast(c0);
        hnxt[tid] = h;                    // hs[q][b] == hs[tid]: coalesced
        hp[(size_t)t * (2 * Hh)] = h;
        __syncthreads();
    }
}

// ---------------- FC head: out[b] = relu(last@fc1^T+b1) @ fc2^T + b2 -------
__global__ void __launch_bounds__(128) fc_head(
    const float* __restrict__ fc1w, const float* __restrict__ fc1b,
    const float* __restrict__ fc2w, const float* __restrict__ fc2b,
    float* __restrict__ out)
{
    __shared__ float last[2 * Hh];
    __shared__ float red[Hh];
    const int b = blockIdx.x, tid = threadIdx.x;
    const float* src = g_h1 + ((size_t)b * Tt + (Tt - 1)) * (2 * Hh);
    last[tid] = src[tid];
    last[tid + Hh] = src[tid + Hh];
    __syncthreads();
    float s = fc1b[tid];
    const float* wr = fc1w + tid * (2 * Hh);
#pragma unroll 8
    for (int k = 0; k < 2 * Hh; ++k) s += wr[k] * last[k];
    red[tid] = fmaxf(s, 0.f) * fc2w[tid];
    __syncthreads();
    for (int st = 64; st > 0; st >>= 1) {
        if (tid < st) red[tid] += red[tid + st];
        __syncthreads();
    }
    if (tid == 0) out[b] = red[0] + fc2b[0];
}

// ---------------- launch ---------------------------------------------------
extern "C" void kernel_launch(void* const* d_in, const int* in_sizes, int n_in,
                              void* d_out, int out_size)
{
    (void)in_sizes; (void)n_in; (void)out_size;
    const float* x     = (const float*)d_in[0];
    const float* Wih0  = (const float*)d_in[1];
    const float* Whh0  = (const float*)d_in[2];
    const float* bih0  = (const float*)d_in[3];
    const float* bhh0  = (const float*)d_in[4];
    const float* Wih0r = (const float*)d_in[5];
    const float* Whh0r = (const float*)d_in[6];
    const float* bih0r = (const float*)d_in[7];
    const float* bhh0r = (const float*)d_in[8];
    const float* Wih1  = (const float*)d_in[9];
    const float* Whh1  = (const float*)d_in[10];
    const float* bih1  = (const float*)d_in[11];
    const float* bhh1  = (const float*)d_in[12];
    const float* Wih1r = (const float*)d_in[13];
    const float* Whh1r = (const float*)d_in[14];
    const float* bih1r = (const float*)d_in[15];
    const float* bhh1r = (const float*)d_in[16];
    const float* fc1w  = (const float*)d_in[17];
    const float* fc1b  = (const float*)d_in[18];
    const float* fc2w  = (const float*)d_in[19];
    const float* fc2b  = (const float*)d_in[20];
    float* out = (float*)d_out;

    const int SMEM = (GH * WSTR + 2 * NB * Hh) * 4;   // 208,896 B
    cudaFuncSetAttribute(lstm_rec, cudaFuncAttributeMaxDynamicSharedMemorySize, SMEM);

    dim3 gg(Bb * Tt / 128, GH / 128, 2);
    dim3 gr(Bb / NB, 2);

    // layer 0
    xg_gemm<<<gg, 256>>>(x, 0, Ii, Wih0, Wih0r, bih0, bhh0, bih0r, bhh0r);
    lstm_rec<<<gr, 512, SMEM>>>(0, Whh0, Whh0r);
    // layer 1 (input = g_h0, K = 256)
    xg_gemm<<<gg, 256>>>(x, 1, 2 * Hh, Wih1, Wih1r, bih1, bhh1, bih1r, bhh1r);
    lstm_rec<<<gr, 512, SMEM>>>(1, Whh1, Whh1r);
    // head
    fc_head<<<Bb, Hh>>>(fc1w, fc1b, fc2w, fc2b, out);
}

// round 9
// speedup vs baseline: 1.2660x; 1.2660x over previous
#include <cuda_runtime.h>
#include <math.h>

// Problem constants
#define Bb 256
#define Tt 512
#define Ii 64
#define Hh 128
#define GH 512          // 4*H
#define NB 4            // batch samples per recurrence CTA
#define KS 96           // weight cols kept in smem (cols 96..127 live in regs)
#define WSTR 100        // padded smem row stride (words): 25 quads -> conflict-free LDS.128

typedef unsigned long long ull;

// permutation: gate row n -> slot p(n) so that quad lanes own rows {j,j+128,j+256,j+384}
// (applied only to the smem weight copy inside lstm_rec; g_xg stays natural order)
#define PSLOT(n) ((((n) & 127) << 2) | ((n) >> 7))

// ---------------- scratch (device globals; no cudaMalloc allowed) ----------
__device__ float g_xg[2 * Bb * Tt * GH];     // [dir][b][t][4H]  (natural order)
__device__ float g_h0[Bb * Tt * 2 * Hh];     // layer0 output [b][t][2H]
__device__ float g_h1[Bb * Tt * 2 * Hh];     // layer1 output [b][t][2H]

// ---------------- f32x2 helpers (packed fp32 FMA, sm_100+) -----------------
__device__ __forceinline__ ull pk2(float x, float y) {
    ull r; asm("mov.b64 %0, {%1, %2};" : "=l"(r) : "f"(x), "f"(y)); return r;
}
__device__ __forceinline__ void fma2(ull& d, ull a, ull b) {
    asm("fma.rn.f32x2 %0, %1, %2, %0;" : "+l"(d) : "l"(a), "l"(b));
}
__device__ __forceinline__ void unpk2(ull v, float& x, float& y) {
    asm("mov.b64 {%0, %1}, %2;" : "=f"(x), "=f"(y) : "l"(v));
}
__device__ __forceinline__ float f4c(const float4 v, int i) {
    return i == 0 ? v.x : i == 1 ? v.y : i == 2 ? v.z : v.w;
}
// fast activations: __expf + MUFU.RCP; proven rel err ~3.5e-7 end-to-end
__device__ __forceinline__ float sigf(float x) {
    float e = __expf(-x);
    return __fdividef(1.0f, 1.0f + e);
}
__device__ __forceinline__ float tanhfast(float x) {
    float e = __expf(-2.0f * x);
    return __fdividef(1.0f - e, 1.0f + e);
}

// ---------------- xg GEMM v2: Y[dir][m][n] = X[m,:]·W[n,:] + bih[n]+bhh[n] -
// CTA tile 128m x 128n, BK=16, 256 threads, thread tile 8x8 (4+4 split).
// Double-buffered smem; vectorized float4 epilogue (coalesced, natural order).
__global__ void __launch_bounds__(256) xg_gemm(
    const float* __restrict__ X0, int layer, int K,
    const float* __restrict__ W0, const float* __restrict__ W1,
    const float* __restrict__ bi0, const float* __restrict__ bh0,
    const float* __restrict__ bi1, const float* __restrict__ bh1)
{
    const int M = Bb * Tt;
    __shared__ float Xs[2][16][132];
    __shared__ float Ws[2][16][132];
    const float* X  = layer ? g_h0 : X0;
    const int dir   = blockIdx.z;
    const float* W  = dir ? W1 : W0;
    const float* bi = dir ? bi1 : bi0;
    const float* bh = dir ? bh1 : bh0;
    const int m0 = blockIdx.x * 128;
    const int n0 = blockIdx.y * 128;
    const int tid = threadIdx.x;
    const int tx = tid & 15, ty = tid >> 4;
    const int gr = tid & 127, qh = tid >> 7;   // global-load row, k-half

    const float* Xp = X + (size_t)(m0 + gr) * K + 8 * qh;
    const float* Wp = W + (size_t)(n0 + gr) * K + 8 * qh;

    float4 xr0 = *(const float4*)Xp, xr1 = *(const float4*)(Xp + 4);
    float4 wr0 = *(const float4*)Wp, wr1 = *(const float4*)(Wp + 4);
    const int kq = 8 * qh;
    Xs[0][kq+0][gr]=xr0.x; Xs[0][kq+1][gr]=xr0.y; Xs[0][kq+2][gr]=xr0.z; Xs[0][kq+3][gr]=xr0.w;
    Xs[0][kq+4][gr]=xr1.x; Xs[0][kq+5][gr]=xr1.y; Xs[0][kq+6][gr]=xr1.z; Xs[0][kq+7][gr]=xr1.w;
    Ws[0][kq+0][gr]=wr0.x; Ws[0][kq+1][gr]=wr0.y; Ws[0][kq+2][gr]=wr0.z; Ws[0][kq+3][gr]=wr0.w;
    Ws[0][kq+4][gr]=wr1.x; Ws[0][kq+5][gr]=wr1.y; Ws[0][kq+6][gr]=wr1.z; Ws[0][kq+7][gr]=wr1.w;
    __syncthreads();

    ull acc[8][4];
#pragma unroll
    for (int i = 0; i < 8; i++)
#pragma unroll
        for (int j = 0; j < 4; j++) acc[i][j] = 0ull;

    const int NIT = K / 16;
    for (int it = 0; it < NIT; ++it) {
        const int cur = it & 1;
        if (it + 1 < NIT) {
            const float* xp = Xp + (it + 1) * 16;
            const float* wp = Wp + (it + 1) * 16;
            xr0 = *(const float4*)xp; xr1 = *(const float4*)(xp + 4);
            wr0 = *(const float4*)wp; wr1 = *(const float4*)(wp + 4);
        }
#pragma unroll
        for (int k = 0; k < 16; ++k) {
            float4 xa = *(const float4*)&Xs[cur][k][ty * 4];
            float4 xb = *(const float4*)&Xs[cur][k][64 + ty * 4];
            float4 wa = *(const float4*)&Ws[cur][k][tx * 4];
            float4 wb = *(const float4*)&Ws[cur][k][64 + tx * 4];
            ull p0 = pk2(wa.x, wa.y), p1 = pk2(wa.z, wa.w);
            ull p2 = pk2(wb.x, wb.y), p3 = pk2(wb.z, wb.w);
            ull a;
            a = pk2(xa.x, xa.x);
            fma2(acc[0][0],a,p0); fma2(acc[0][1],a,p1); fma2(acc[0][2],a,p2); fma2(acc[0][3],a,p3);
            a = pk2(xa.y, xa.y);
            fma2(acc[1][0],a,p0); fma2(acc[1][1],a,p1); fma2(acc[1][2],a,p2); fma2(acc[1][3],a,p3);
            a = pk2(xa.z, xa.z);
            fma2(acc[2][0],a,p0); fma2(acc[2][1],a,p1); fma2(acc[2][2],a,p2); fma2(acc[2][3],a,p3);
            a = pk2(xa.w, xa.w);
            fma2(acc[3][0],a,p0); fma2(acc[3][1],a,p1); fma2(acc[3][2],a,p2); fma2(acc[3][3],a,p3);
            a = pk2(xb.x, xb.x);
            fma2(acc[4][0],a,p0); fma2(acc[4][1],a,p1); fma2(acc[4][2],a,p2); fma2(acc[4][3],a,p3);
            a = pk2(xb.y, xb.y);
            fma2(acc[5][0],a,p0); fma2(acc[5][1],a,p1); fma2(acc[5][2],a,p2); fma2(acc[5][3],a,p3);
            a = pk2(xb.z, xb.z);
            fma2(acc[6][0],a,p0); fma2(acc[6][1],a,p1); fma2(acc[6][2],a,p2); fma2(acc[6][3],a,p3);
            a = pk2(xb.w, xb.w);
            fma2(acc[7][0],a,p0); fma2(acc[7][1],a,p1); fma2(acc[7][2],a,p2); fma2(acc[7][3],a,p3);
        }
        if (it + 1 < NIT) {
            const int nxt = cur ^ 1;
            Xs[nxt][kq+0][gr]=xr0.x; Xs[nxt][kq+1][gr]=xr0.y; Xs[nxt][kq+2][gr]=xr0.z; Xs[nxt][kq+3][gr]=xr0.w;
            Xs[nxt][kq+4][gr]=xr1.x; Xs[nxt][kq+5][gr]=xr1.y; Xs[nxt][kq+6][gr]=xr1.z; Xs[nxt][kq+7][gr]=xr1.w;
            Ws[nxt][kq+0][gr]=wr0.x; Ws[nxt][kq+1][gr]=wr0.y; Ws[nxt][kq+2][gr]=wr0.z; Ws[nxt][kq+3][gr]=wr0.w;
            Ws[nxt][kq+4][gr]=wr1.x; Ws[nxt][kq+5][gr]=wr1.y; Ws[nxt][kq+6][gr]=wr1.z; Ws[nxt][kq+7][gr]=wr1.w;
        }
        __syncthreads();
    }

    const int na = n0 + tx * 4, nb = na + 64;
    float bsA[4], bsB[4];
#pragma unroll
    for (int j = 0; j < 4; j++) {
        bsA[j] = bi[na + j] + bh[na + j];
        bsB[j] = bi[nb + j] + bh[nb + j];
    }
    float* base = g_xg + (size_t)dir * M * GH;
#pragma unroll
    for (int i = 0; i < 8; ++i) {
        const int m = m0 + (i < 4 ? ty * 4 + i : 64 + ty * 4 + (i - 4));
        float* y = base + (size_t)m * GH;
        float4 v;
        unpk2(acc[i][0], v.x, v.y); unpk2(acc[i][1], v.z, v.w);
        v.x += bsA[0]; v.y += bsA[1]; v.z += bsA[2]; v.w += bsA[3];
        *(float4*)(y + na) = v;
        unpk2(acc[i][2], v.x, v.y); unpk2(acc[i][3], v.z, v.w);
        v.x += bsB[0]; v.y += bsB[1]; v.z += bsB[2]; v.w += bsB[3];
        *(float4*)(y + nb) = v;
    }
}

// ---------------- LSTM recurrence: one CTA = (direction, 4 batch samples) --
// 512 threads. Thread tid owns gate row rthr = (tid&3)*128 + (tid>>2), whose
// weights sit at smem slot tid (PSLOT permutation applied at load time).
// One barrier per step: gate exchange via 3 shfl.xor in the lane quad;
// hs ping-pongs (WAR safety). xg read as a sector-coalesced gather (each
// 8-lane gate-group reads 8 consecutive floats = one full 32B sector).
__global__ void __launch_bounds__(512, 1) lstm_rec(
    int layer,
    const float* __restrict__ Wf, const float* __restrict__ Wr)
{
    extern __shared__ float sm[];
    float* sW  = sm;                       // 512 * WSTR floats (permuted slots)
    float* hsA = sm + GH * WSTR;           // ping [128][NB]
    float* hsB = hsA + NB * Hh;            // pong [128][NB]

    const int dir = blockIdx.y;
    const int b0  = blockIdx.x * NB;
    const float* Whh = dir ? Wr : Wf;
    float* hout = layer ? g_h1 : g_h0;
    const float* xg = g_xg + (size_t)dir * Bb * Tt * GH;
    const int tid  = threadIdx.x;
    const int lane = tid & 31, wid = tid >> 5;

    // weights: cols [0,96) of every row into smem at PERMUTED slot
    {
        const float4* src = (const float4*)Whh;   // 32 float4 per row
        for (int r = wid; r < GH; r += 16) {
            const int ps = PSLOT(r);
            if (lane < 24)
                *(float4*)(sW + ps * WSTR + lane * 4) = src[r * 32 + lane];
        }
        for (int i = tid; i < 2 * NB * Hh; i += 512) hsA[i] = 0.f;
    }
    // this thread's row: cols [96,128) in registers
    const int rthr = ((tid & 3) << 7) | (tid >> 2);
    float4 wreg[8];
    {
        const float4* src = (const float4*)(Whh + (size_t)rthr * Hh);
#pragma unroll
        for (int j = 0; j < 8; ++j) wreg[j] = src[24 + j];
    }
    const int e = tid & 3;                // gate type AND owned batch
    const int q = tid >> 2;               // hidden index j
    const bool p0 = (e & 1) != 0, p1 = (e & 2) != 0;
    float c0 = 0.f;
    const float* wrow = sW + tid * WSTR;
    float* hp = hout + (size_t)(b0 + e) * Tt * (2 * Hh) + dir * Hh + q;
    __syncthreads();

    const size_t TG = (size_t)Tt * GH;
    for (int s = 0; s < Tt; ++s) {
        const int t = dir ? (Tt - 1 - s) : s;
        const float* hcur = (s & 1) ? hsB : hsA;
        float* hnxt       = (s & 1) ? hsA : hsB;
        const size_t xb = (size_t)b0 * TG + (size_t)t * GH + rthr;
        // prefetch xg for this gate row (sector-coalesced gather), 4 batches
        float x0 = xg[xb];
        float x1 = xg[xb + TG];
        float x2 = xg[xb + 2 * TG];
        float x3 = xg[xb + 3 * TG];

        ull a01 = 0, a23 = 0;
#pragma unroll 6
        for (int k = 0; k < KS; k += 4) {
            float4 wv = *(const float4*)(wrow + k);
#pragma unroll
            for (int kk = 0; kk < 4; ++kk) {
                float4 hv = *(const float4*)(hcur + 4 * (k + kk));
                ull h01 = pk2(hv.x, hv.y), h23 = pk2(hv.z, hv.w);
                float w1 = f4c(wv, kk);
                ull am = pk2(w1, w1);
                fma2(a01, am, h01); fma2(a23, am, h23);
            }
        }
#pragma unroll
        for (int j = 0; j < 8; ++j) {
            float4 wv = wreg[j];
            const int k = KS + 4 * j;
#pragma unroll
            for (int kk = 0; kk < 4; ++kk) {
                float4 hv = *(const float4*)(hcur + 4 * (k + kk));
                ull h01 = pk2(hv.x, hv.y), h23 = pk2(hv.z, hv.w);
                float w1 = f4c(wv, kk);
                ull am = pk2(w1, w1);
                fma2(a01, am, h01); fma2(a23, am, h23);
            }
        }

        float a0, a1, a2, a3;
        unpk2(a01, a0, a1); unpk2(a23, a2, a3);
        a0 += x0; a1 += x1; a2 += x2; a3 += x3;   // preact: gate e, batches 0..3

        // 4x4 quad transpose: thread ends with gates 0..3 for batch e.
        float own = p1 ? (p0 ? a3 : a2) : (p0 ? a1 : a0);   // a[e]
        float s1  = p1 ? (p0 ? a2 : a3) : (p0 ? a0 : a1);   // a[e^1]
        float s2  = p1 ? (p0 ? a1 : a0) : (p0 ? a3 : a2);   // a[e^2]
        float s3  = p1 ? (p0 ? a0 : a1) : (p0 ? a2 : a3);   // a[e^3]
        float v1 = __shfl_xor_sync(0xffffffffu, s1, 1);
        float v2 = __shfl_xor_sync(0xffffffffu, s2, 2);
        float v3 = __shfl_xor_sync(0xffffffffu, s3, 3);
        // G_i = v[e^i] with v[] = {own, v1, v2, v3}
        float G0 = p1 ? (p0 ? v3 : v2) : (p0 ? v1 : own);
        float G1 = p1 ? (p0 ? v2 : v3) : (p0 ? own : v1);
        float G2 = p1 ? (p0 ? v1 : own) : (p0 ? v3 : v2);
        float G3 = p1 ? (p0 ? own : v1) : (p0 ? v2 : v3);

        // elementwise: this thread owns (batch e, hidden q)
        c0 = sigf(G1) * c0 + sigf(G0) * tanhfast(G2);
        float h = sigf(G3) * tanhfast(c0);
        hnxt[tid] = h;                    // hs[q][b] == hs[tid]: coalesced
        hp[(size_t)t * (2 * Hh)] = h;
        __syncthreads();
    }
}

// ---------------- FC head: out[b] = relu(last@fc1^T+b1) @ fc2^T + b2 -------
__global__ void __launch_bounds__(128) fc_head(
    const float* __restrict__ fc1w, const float* __restrict__ fc1b,
    const float* __restrict__ fc2w, const float* __restrict__ fc2b,
    float* __restrict__ out)
{
    __shared__ float last[2 * Hh];
    __shared__ float red[Hh];
    const int b = blockIdx.x, tid = threadIdx.x;
    const float* src = g_h1 + ((size_t)b * Tt + (Tt - 1)) * (2 * Hh);
    last[tid] = src[tid];
    last[tid + Hh] = src[tid + Hh];
    __syncthreads();
    float s = fc1b[tid];
    const float* wr = fc1w + tid * (2 * Hh);
#pragma unroll 8
    for (int k = 0; k < 2 * Hh; ++k) s += wr[k] * last[k];
    red[tid] = fmaxf(s, 0.f) * fc2w[tid];
    __syncthreads();
    for (int st = 64; st > 0; st >>= 1) {
        if (tid < st) red[tid] += red[tid + st];
        __syncthreads();
    }
    if (tid == 0) out[b] = red[0] + fc2b[0];
}

// ---------------- launch ---------------------------------------------------
extern "C" void kernel_launch(void* const* d_in, const int* in_sizes, int n_in,
                              void* d_out, int out_size)
{
    (void)in_sizes; (void)n_in; (void)out_size;
    const float* x     = (const float*)d_in[0];
    const float* Wih0  = (const float*)d_in[1];
    const float* Whh0  = (const float*)d_in[2];
    const float* bih0  = (const float*)d_in[3];
    const float* bhh0  = (const float*)d_in[4];
    const float* Wih0r = (const float*)d_in[5];
    const float* Whh0r = (const float*)d_in[6];
    const float* bih0r = (const float*)d_in[7];
    const float* bhh0r = (const float*)d_in[8];
    const float* Wih1  = (const float*)d_in[9];
    const float* Whh1  = (const float*)d_in[10];
    const float* bih1  = (const float*)d_in[11];
    const float* bhh1  = (const float*)d_in[12];
    const float* Wih1r = (const float*)d_in[13];
    const float* Whh1r = (const float*)d_in[14];
    const float* bih1r = (const float*)d_in[15];
    const float* bhh1r = (const float*)d_in[16];
    const float* fc1w  = (const float*)d_in[17];
    const float* fc1b  = (const float*)d_in[18];
    const float* fc2w  = (const float*)d_in[19];
    const float* fc2b  = (const float*)d_in[20];
    float* out = (float*)d_out;

    const int SMEM = (GH * WSTR + 2 * NB * Hh) * 4;   // 208,896 B
    cudaFuncSetAttribute(lstm_rec, cudaFuncAttributeMaxDynamicSharedMemorySize, SMEM);

    dim3 gg(Bb * Tt / 128, GH / 128, 2);
    dim3 gr(Bb / NB, 2);

    // layer 0
    xg_gemm<<<gg, 256>>>(x, 0, Ii, Wih0, Wih0r, bih0, bhh0, bih0r, bhh0r);
    lstm_rec<<<gr, 512, SMEM>>>(0, Whh0, Whh0r);
    // layer 1 (input = g_h0, K = 256)
    xg_gemm<<<gg, 256>>>(x, 1, 2 * Hh, Wih1, Wih1r, bih1, bhh1, bih1r, bhh1r);
    lstm_rec<<<gr, 512, SMEM>>>(1, Whh1, Whh1r);
    // head
    fc_head<<<Bb, Hh>>>(fc1w, fc1b, fc2w, fc2b, out);
}

// round 10
// speedup vs baseline: 1.4454x; 1.1418x over previous
#include <cuda_runtime.h>
#include <math.h>

// Problem constants
#define Bb 256
#define Tt 512
#define Ii 64
#define Hh 128
#define GH 512          // 4*H
#define NB 4            // batch samples per recurrence CTA

// weight smem chunk layout: chunk = (row, kh) holds 24 fp32 (cols [32kh,32kh+24))
// chunks grouped by 8: strides 28,28,...,28,24 -> every 8-lane phase hits
// distinct bank quads ({0,7,6,5,4,3,2,1} pattern). 2048 chunks, 256 groups.
#define CHW 28
#define GRPW 220
#define WWORDS (256 * GRPW)        // 56320 words = 225280 B
#define HSW 544                    // hs buffer words (128 ks * 4 + 8-word gap / 32 ks)

typedef unsigned long long ull;

__device__ __forceinline__ int wchunk(int idx) {
    return (idx >> 3) * GRPW + (idx & 7) * CHW;
}

// ---------------- scratch (device globals; no cudaMalloc allowed) ----------
__device__ float g_xg[2 * Bb * Tt * GH];     // [dir][b][t][4H]  (natural order)
__device__ float g_h0[Bb * Tt * 2 * Hh];     // layer0 output [b][t][2H]
__device__ float g_h1[Bb * Tt * 2 * Hh];     // layer1 output [b][t][2H]

// ---------------- f32x2 helpers (packed fp32 FMA, sm_100+) -----------------
__device__ __forceinline__ ull pk2(float x, float y) {
    ull r; asm("mov.b64 %0, {%1, %2};" : "=l"(r) : "f"(x), "f"(y)); return r;
}
__device__ __forceinline__ void fma2(ull& d, ull a, ull b) {
    asm("fma.rn.f32x2 %0, %1, %2, %0;" : "+l"(d) : "l"(a), "l"(b));
}
__device__ __forceinline__ ull add2(ull a, ull b) {
    ull r; asm("add.rn.f32x2 %0, %1, %2;" : "=l"(r) : "l"(a), "l"(b)); return r;
}
__device__ __forceinline__ void unpk2(ull v, float& x, float& y) {
    asm("mov.b64 {%0, %1}, %2;" : "=f"(x), "=f"(y) : "l"(v));
}
__device__ __forceinline__ float f4c(const float4 v, int i) {
    return i == 0 ? v.x : i == 1 ? v.y : i == 2 ? v.z : v.w;
}
// fast activations: __expf + MUFU.RCP; proven rel err ~3.5e-7 end-to-end
__device__ __forceinline__ float sigf(float x) {
    float e = __expf(-x);
    return __fdividef(1.0f, 1.0f + e);
}
__device__ __forceinline__ float tanhfast(float x) {
    float e = __expf(-2.0f * x);
    return __fdividef(1.0f - e, 1.0f + e);
}

// ---------------- xg GEMM v2: Y[dir][m][n] = X[m,:]·W[n,:] + bih[n]+bhh[n] -
// CTA tile 128m x 128n, BK=16, 256 threads, thread tile 8x8 (4+4 split).
// Double-buffered smem; vectorized float4 epilogue (coalesced, natural order).
__global__ void __launch_bounds__(256) xg_gemm(
    const float* __restrict__ X0, int layer, int K,
    const float* __restrict__ W0, const float* __restrict__ W1,
    const float* __restrict__ bi0, const float* __restrict__ bh0,
    const float* __restrict__ bi1, const float* __restrict__ bh1)
{
    const int M = Bb * Tt;
    __shared__ float Xs[2][16][132];
    __shared__ float Ws[2][16][132];
    const float* X  = layer ? g_h0 : X0;
    const int dir   = blockIdx.z;
    const float* W  = dir ? W1 : W0;
    const float* bi = dir ? bi1 : bi0;
    const float* bh = dir ? bh1 : bh0;
    const int m0 = blockIdx.x * 128;
    const int n0 = blockIdx.y * 128;
    const int tid = threadIdx.x;
    const int tx = tid & 15, ty = tid >> 4;
    const int gr = tid & 127, qh = tid >> 7;   // global-load row, k-half

    const float* Xp = X + (size_t)(m0 + gr) * K + 8 * qh;
    const float* Wp = W + (size_t)(n0 + gr) * K + 8 * qh;

    float4 xr0 = *(const float4*)Xp, xr1 = *(const float4*)(Xp + 4);
    float4 wr0 = *(const float4*)Wp, wr1 = *(const float4*)(Wp + 4);
    const int kq = 8 * qh;
    Xs[0][kq+0][gr]=xr0.x; Xs[0][kq+1][gr]=xr0.y; Xs[0][kq+2][gr]=xr0.z; Xs[0][kq+3][gr]=xr0.w;
    Xs[0][kq+4][gr]=xr1.x; Xs[0][kq+5][gr]=xr1.y; Xs[0][kq+6][gr]=xr1.z; Xs[0][kq+7][gr]=xr1.w;
    Ws[0][kq+0][gr]=wr0.x; Ws[0][kq+1][gr]=wr0.y; Ws[0][kq+2][gr]=wr0.z; Ws[0][kq+3][gr]=wr0.w;
    Ws[0][kq+4][gr]=wr1.x; Ws[0][kq+5][gr]=wr1.y; Ws[0][kq+6][gr]=wr1.z; Ws[0][kq+7][gr]=wr1.w;
    __syncthreads();

    ull acc[8][4];
#pragma unroll
    for (int i = 0; i < 8; i++)
#pragma unroll
        for (int j = 0; j < 4; j++) acc[i][j] = 0ull;

    const int NIT = K / 16;
    for (int it = 0; it < NIT; ++it) {
        const int cur = it & 1;
        if (it + 1 < NIT) {
            const float* xp = Xp + (it + 1) * 16;
            const float* wp = Wp + (it + 1) * 16;
            xr0 = *(const float4*)xp; xr1 = *(const float4*)(xp + 4);
            wr0 = *(const float4*)wp; wr1 = *(const float4*)(wp + 4);
        }
#pragma unroll
        for (int k = 0; k < 16; ++k) {
            float4 xa = *(const float4*)&Xs[cur][k][ty * 4];
            float4 xb = *(const float4*)&Xs[cur][k][64 + ty * 4];
            float4 wa = *(const float4*)&Ws[cur][k][tx * 4];
            float4 wb = *(const float4*)&Ws[cur][k][64 + tx * 4];
            ull p0 = pk2(wa.x, wa.y), p1 = pk2(wa.z, wa.w);
            ull p2 = pk2(wb.x, wb.y), p3 = pk2(wb.z, wb.w);
            ull a;
            a = pk2(xa.x, xa.x);
            fma2(acc[0][0],a,p0); fma2(acc[0][1],a,p1); fma2(acc[0][2],a,p2); fma2(acc[0][3],a,p3);
            a = pk2(xa.y, xa.y);
            fma2(acc[1][0],a,p0); fma2(acc[1][1],a,p1); fma2(acc[1][2],a,p2); fma2(acc[1][3],a,p3);
            a = pk2(xa.z, xa.z);
            fma2(acc[2][0],a,p0); fma2(acc[2][1],a,p1); fma2(acc[2][2],a,p2); fma2(acc[2][3],a,p3);
            a = pk2(xa.w, xa.w);
            fma2(acc[3][0],a,p0); fma2(acc[3][1],a,p1); fma2(acc[3][2],a,p2); fma2(acc[3][3],a,p3);
            a = pk2(xb.x, xb.x);
            fma2(acc[4][0],a,p0); fma2(acc[4][1],a,p1); fma2(acc[4][2],a,p2); fma2(acc[4][3],a,p3);
            a = pk2(xb.y, xb.y);
            fma2(acc[5][0],a,p0); fma2(acc[5][1],a,p1); fma2(acc[5][2],a,p2); fma2(acc[5][3],a,p3);
            a = pk2(xb.z, xb.z);
            fma2(acc[6][0],a,p0); fma2(acc[6][1],a,p1); fma2(acc[6][2],a,p2); fma2(acc[6][3],a,p3);
            a = pk2(xb.w, xb.w);
            fma2(acc[7][0],a,p0); fma2(acc[7][1],a,p1); fma2(acc[7][2],a,p2); fma2(acc[7][3],a,p3);
        }
        if (it + 1 < NIT) {
            const int nxt = cur ^ 1;
            Xs[nxt][kq+0][gr]=xr0.x; Xs[nxt][kq+1][gr]=xr0.y; Xs[nxt][kq+2][gr]=xr0.z; Xs[nxt][kq+3][gr]=xr0.w;
            Xs[nxt][kq+4][gr]=xr1.x; Xs[nxt][kq+5][gr]=xr1.y; Xs[nxt][kq+6][gr]=xr1.z; Xs[nxt][kq+7][gr]=xr1.w;
            Ws[nxt][kq+0][gr]=wr0.x; Ws[nxt][kq+1][gr]=wr0.y; Ws[nxt][kq+2][gr]=wr0.z; Ws[nxt][kq+3][gr]=wr0.w;
            Ws[nxt][kq+4][gr]=wr1.x; Ws[nxt][kq+5][gr]=wr1.y; Ws[nxt][kq+6][gr]=wr1.z; Ws[nxt][kq+7][gr]=wr1.w;
        }
        __syncthreads();
    }

    const int na = n0 + tx * 4, nb = na + 64;
    float bsA[4], bsB[4];
#pragma unroll
    for (int j = 0; j < 4; j++) {
        bsA[j] = bi[na + j] + bh[na + j];
        bsB[j] = bi[nb + j] + bh[nb + j];
    }
    float* base = g_xg + (size_t)dir * M * GH;
#pragma unroll
    for (int i = 0; i < 8; ++i) {
        const int m = m0 + (i < 4 ? ty * 4 + i : 64 + ty * 4 + (i - 4));
        float* y = base + (size_t)m * GH;
        float4 v;
        unpk2(acc[i][0], v.x, v.y); unpk2(acc[i][1], v.z, v.w);
        v.x += bsA[0]; v.y += bsA[1]; v.z += bsA[2]; v.w += bsA[3];
        *(float4*)(y + na) = v;
        unpk2(acc[i][2], v.x, v.y); unpk2(acc[i][3], v.z, v.w);
        v.x += bsB[0]; v.y += bsB[1]; v.z += bsB[2]; v.w += bsB[3];
        *(float4*)(y + nb) = v;
    }
}

// ---------------- LSTM recurrence: one CTA = (direction, 4 batch samples) --
// 512 threads. Thread (q = tid>>2, kh = tid&3) computes partial dots over
// k in [32kh, 32kh+32) for ALL 4 gate rows {q, q+128, q+256, q+384}, 4
// batches. Quad shuffle reduce-scatter over kh leaves thread with gates
// 0..3 for (batch kh, unit q). Weights: 24 cols/row/quarter in smem
// (conflict-free chunked layout), 8 in registers. hs[k][b] with 8-word gap
// every 32 ks (distinct quads per kh). One barrier/step; hs ping-pongs.
__global__ void __launch_bounds__(512, 1) lstm_rec(
    int layer,
    const float* __restrict__ Wf, const float* __restrict__ Wr)
{
    extern __shared__ float sm[];
    float* sW  = sm;                       // WWORDS
    float* hsA = sm + WWORDS;              // HSW words
    float* hsB = hsA + HSW;

    const int dir = blockIdx.y;
    const int b0  = blockIdx.x * NB;
    const float* Whh = dir ? Wr : Wf;
    float* hout = layer ? g_h1 : g_h0;
    const float* xg = g_xg + (size_t)dir * Bb * Tt * GH;
    const int tid = threadIdx.x;
    const int q = tid >> 2, kh = tid & 3;

    // cooperative weight load: 2048 chunks x 6 float4
    for (int i = tid; i < 2048 * 6; i += 512) {
        const int ch = i / 6, fq = i - ch * 6;
        const int r = ch >> 2, kq = ch & 3;
        float4 v = *(const float4*)(Whh + (size_t)r * Hh + kq * 32 + fq * 4);
        *(float4*)(sW + wchunk(ch) + fq * 4) = v;
    }
    for (int i = tid; i < 2 * HSW; i += 512) hsA[i] = 0.f;

    // register weights: rows g*128+q, cols [32kh+24, 32kh+32)
    float4 wra[4], wrb[4];
#pragma unroll
    for (int g = 0; g < 4; ++g) {
        const float* src = Whh + (size_t)(g * Hh + q) * Hh + 32 * kh + 24;
        wra[g] = *(const float4*)src;
        wrb[g] = *(const float4*)(src + 4);
    }

    const float* wp = sW + wchunk(4 * q + kh);   // g offsets: +14080*g words
    const int hb = 136 * kh;                     // hs word base for this k-quarter
    const int mypair = kh >> 1, mybit = kh & 1;
    float c0 = 0.f;
    float* hp = hout + (size_t)(b0 + kh) * Tt * (2 * Hh) + dir * Hh + q;
    const float* xrow = xg + (size_t)(b0 + kh) * Tt * GH + q;
    __syncthreads();

    for (int s = 0; s < Tt; ++s) {
        const int t = dir ? (Tt - 1 - s) : s;
        const float* hcur = (s & 1) ? hsB : hsA;
        float* hnxt       = (s & 1) ? hsA : hsB;
        const float* xt = xrow + (size_t)t * GH;
        float xq0 = xt[0], xq1 = xt[128], xq2 = xt[256], xq3 = xt[384];

        ull A01[4] = {0,0,0,0}, A23[4] = {0,0,0,0};   // [gate], batch pairs
        const float* hq = hcur + hb;
#pragma unroll
        for (int jf = 0; jf < 6; ++jf) {
            float4 w0 = *(const float4*)(wp + jf * 4);
            float4 w1 = *(const float4*)(wp + 14080 + jf * 4);
            float4 w2 = *(const float4*)(wp + 28160 + jf * 4);
            float4 w3 = *(const float4*)(wp + 42240 + jf * 4);
#pragma unroll
            for (int kk = 0; kk < 4; ++kk) {
                float4 hv = *(const float4*)(hq + (jf * 4 + kk) * 4);
                ull h01 = pk2(hv.x, hv.y), h23 = pk2(hv.z, hv.w);
                ull m0 = pk2(f4c(w0, kk), f4c(w0, kk));
                ull m1 = pk2(f4c(w1, kk), f4c(w1, kk));
                ull m2 = pk2(f4c(w2, kk), f4c(w2, kk));
                ull m3 = pk2(f4c(w3, kk), f4c(w3, kk));
                fma2(A01[0], m0, h01); fma2(A23[0], m0, h23);
                fma2(A01[1], m1, h01); fma2(A23[1], m1, h23);
                fma2(A01[2], m2, h01); fma2(A23[2], m2, h23);
                fma2(A01[3], m3, h01); fma2(A23[3], m3, h23);
            }
        }
#pragma unroll
        for (int jr = 0; jr < 8; ++jr) {
            float4 hv = *(const float4*)(hq + (24 + jr) * 4);
            ull h01 = pk2(hv.x, hv.y), h23 = pk2(hv.z, hv.w);
            float f0 = jr < 4 ? f4c(wra[0], jr) : f4c(wrb[0], jr - 4);
            float f1 = jr < 4 ? f4c(wra[1], jr) : f4c(wrb[1], jr - 4);
            float f2 = jr < 4 ? f4c(wra[2], jr) : f4c(wrb[2], jr - 4);
            float f3 = jr < 4 ? f4c(wra[3], jr) : f4c(wrb[3], jr - 4);
            ull m0 = pk2(f0, f0), m1 = pk2(f1, f1), m2 = pk2(f2, f2), m3 = pk2(f3, f3);
            fma2(A01[0], m0, h01); fma2(A23[0], m0, h23);
            fma2(A01[1], m1, h01); fma2(A23[1], m1, h23);
            fma2(A01[2], m2, h01); fma2(A23[2], m2, h23);
            fma2(A01[3], m3, h01); fma2(A23[3], m3, h23);
        }

        // quad reduce-scatter over kh: end with gates 0..3 for batch kh
        ull R[4];
#pragma unroll
        for (int g = 0; g < 4; ++g) {
            ull snd  = mypair ? A01[g] : A23[g];   // pair partner needs
            ull keep = mypair ? A23[g] : A01[g];   // pair I need
            ull rcv = __shfl_xor_sync(0xffffffffu, snd, 2);
            R[g] = add2(keep, rcv);
        }
#pragma unroll
        for (int g = 0; g < 4; ++g) {
            ull rcv = __shfl_xor_sync(0xffffffffu, R[g], 1);
            R[g] = add2(R[g], rcv);
        }
        float G0, G1, G2, G3;
        {
            float lo, hi;
            unpk2(R[0], lo, hi); G0 = mybit ? hi : lo;
            unpk2(R[1], lo, hi); G1 = mybit ? hi : lo;
            unpk2(R[2], lo, hi); G2 = mybit ? hi : lo;
            unpk2(R[3], lo, hi); G3 = mybit ? hi : lo;
        }
        G0 += xq0; G1 += xq1; G2 += xq2; G3 += xq3;

        // elementwise: (batch kh, unit q)
        c0 = sigf(G1) * c0 + sigf(G0) * tanhfast(G2);
        float h = sigf(G3) * tanhfast(c0);
        hnxt[4 * q + 8 * (q >> 5) + kh] = h;
        hp[(size_t)t * (2 * Hh)] = h;
        __syncthreads();
    }
}

// ---------------- FC head: out[b] = relu(last@fc1^T+b1) @ fc2^T + b2 -------
__global__ void __launch_bounds__(128) fc_head(
    const float* __restrict__ fc1w, const float* __restrict__ fc1b,
    const float* __restrict__ fc2w, const float* __restrict__ fc2b,
    float* __restrict__ out)
{
    __shared__ float last[2 * Hh];
    __shared__ float red[Hh];
    const int b = blockIdx.x, tid = threadIdx.x;
    const float* src = g_h1 + ((size_t)b * Tt + (Tt - 1)) * (2 * Hh);
    last[tid] = src[tid];
    last[tid + Hh] = src[tid + Hh];
    __syncthreads();
    float s = fc1b[tid];
    const float* wr = fc1w + tid * (2 * Hh);
#pragma unroll 8
    for (int k = 0; k < 2 * Hh; ++k) s += wr[k] * last[k];
    red[tid] = fmaxf(s, 0.f) * fc2w[tid];
    __syncthreads();
    for (int st = 64; st > 0; st >>= 1) {
        if (tid < st) red[tid] += red[tid + st];
        __syncthreads();
    }
    if (tid == 0) out[b] = red[0] + fc2b[0];
}

// ---------------- launch ---------------------------------------------------
extern "C" void kernel_launch(void* const* d_in, const int* in_sizes, int n_in,
                              void* d_out, int out_size)
{
    (void)in_sizes; (void)n_in; (void)out_size;
    const float* x     = (const float*)d_in[0];
    const float* Wih0  = (const float*)d_in[1];
    const float* Whh0  = (const float*)d_in[2];
    const float* bih0  = (const float*)d_in[3];
    const float* bhh0  = (const float*)d_in[4];
    const float* Wih0r = (const float*)d_in[5];
    const float* Whh0r = (const float*)d_in[6];
    const float* bih0r = (const float*)d_in[7];
    const float* bhh0r = (const float*)d_in[8];
    const float* Wih1  = (const float*)d_in[9];
    const float* Whh1  = (const float*)d_in[10];
    const float* bih1  = (const float*)d_in[11];
    const float* bhh1  = (const float*)d_in[12];
    const float* Wih1r = (const float*)d_in[13];
    const float* Whh1r = (const float*)d_in[14];
    const float* bih1r = (const float*)d_in[15];
    const float* bhh1r = (const float*)d_in[16];
    const float* fc1w  = (const float*)d_in[17];
    const float* fc1b  = (const float*)d_in[18];
    const float* fc2w  = (const float*)d_in[19];
    const float* fc2b  = (const float*)d_in[20];
    float* out = (float*)d_out;

    const int SMEMR = (WWORDS + 2 * HSW) * 4;   // 229,632 B <= 232,448 cap
    cudaFuncSetAttribute(lstm_rec, cudaFuncAttributeMaxDynamicSharedMemorySize, SMEMR);

    dim3 gg(Bb * Tt / 128, GH / 128, 2);
    dim3 gr(Bb / NB, 2);

    // layer 0
    xg_gemm<<<gg, 256>>>(x, 0, Ii, Wih0, Wih0r, bih0, bhh0, bih0r, bhh0r);
    lstm_rec<<<gr, 512, SMEMR>>>(0, Whh0, Whh0r);
    // layer 1 (input = g_h0, K = 256)
    xg_gemm<<<gg, 256>>>(x, 1, 2 * Hh, Wih1, Wih1r, bih1, bhh1, bih1r, bhh1r);
    lstm_rec<<<gr, 512, SMEMR>>>(1, Whh1, Whh1r);
    // head
    fc_head<<<Bb, Hh>>>(fc1w, fc1b, fc2w, fc2b, out);
}

// round 12
// speedup vs baseline: 1.6185x; 1.1198x over previous
#include <cuda_runtime.h>
#include <math.h>

// Problem constants
#define Bb 256
#define Tt 512
#define Ii 64
#define Hh 128
#define GH 512          // 4*H
#define NB 4            // batch samples per recurrence CTA

// weight smem chunk layout: chunk = (row, kh) holds 24 fp32 (cols [32kh,32kh+24))
// chunks grouped by 8: strides 28,...,28,24 -> every 8-lane phase hits
// distinct bank quads. 2048 chunks, 256 groups.
#define CHW 28
#define GRPW 220
#define WWORDS (256 * GRPW)        // 56320 words = 225280 B
#define HSW 544                    // hs buffer words (128 ks * 4 + 8-word gap / 32 ks)

typedef unsigned long long ull;

__device__ __forceinline__ int wchunk(int idx) {
    return (idx >> 3) * GRPW + (idx & 7) * CHW;
}

// ---------------- scratch (device globals; no cudaMalloc allowed) ----------
__device__ float g_xg[2 * Bb * Tt * GH];     // [dir][b][t][4H]  (natural order)
__device__ float g_h0[Bb * Tt * 2 * Hh];     // layer0 output [b][t][2H]
__device__ float g_h1[Bb * Tt * 2 * Hh];     // layer1 output (only t=T-1 valid)

// ---------------- f32x2 helpers (packed fp32 FMA, sm_100+) -----------------
__device__ __forceinline__ ull pk2(float x, float y) {
    ull r; asm("mov.b64 %0, {%1, %2};" : "=l"(r) : "f"(x), "f"(y)); return r;
}
__device__ __forceinline__ void fma2(ull& d, ull a, ull b) {
    asm("fma.rn.f32x2 %0, %1, %2, %0;" : "+l"(d) : "l"(a), "l"(b));
}
__device__ __forceinline__ ull add2(ull a, ull b) {
    ull r; asm("add.rn.f32x2 %0, %1, %2;" : "=l"(r) : "l"(a), "l"(b)); return r;
}
__device__ __forceinline__ void unpk2(ull v, float& x, float& y) {
    asm("mov.b64 {%0, %1}, %2;" : "=f"(x), "=f"(y) : "l"(v));
}
__device__ __forceinline__ float f4c(const float4 v, int i) {
    return i == 0 ? v.x : i == 1 ? v.y : i == 2 ? v.z : v.w;
}
// fast activations: __expf + MUFU.RCP; proven rel err ~3.5e-7 end-to-end
__device__ __forceinline__ float sigf(float x) {
    float e = __expf(-x);
    return __fdividef(1.0f, 1.0f + e);
}
__device__ __forceinline__ float tanhfast(float x) {
    float e = __expf(-2.0f * x);
    return __fdividef(1.0f - e, 1.0f + e);
}

// ---------------- xg GEMM v2: Y[dir][m][n] = X[m,:]·W[n,:] + bih[n]+bhh[n] -
// CTA tile 128m x 128n, BK=16, 256 threads, thread tile 8x8 (4+4 split).
// Double-buffered smem; vectorized float4 epilogue. min 2 CTAs/SM (reg cap 128)
// so each SMSP has 4 warps to hide LDS latency on the fma2 stream.
__global__ void __launch_bounds__(256, 2) xg_gemm(
    const float* __restrict__ X0, int layer, int K,
    const float* __restrict__ W0, const float* __restrict__ W1,
    const float* __restrict__ bi0, const float* __restrict__ bh0,
    const float* __restrict__ bi1, const float* __restrict__ bh1)
{
    const int M = Bb * Tt;
    __shared__ float Xs[2][16][132];
    __shared__ float Ws[2][16][132];
    const float* X  = layer ? g_h0 : X0;
    const int dir   = blockIdx.z;
    const float* W  = dir ? W1 : W0;
    const float* bi = dir ? bi1 : bi0;
    const float* bh = dir ? bh1 : bh0;
    const int m0 = blockIdx.x * 128;
    const int n0 = blockIdx.y * 128;
    const int tid = threadIdx.x;
    const int tx = tid & 15, ty = tid >> 4;
    const int gr = tid & 127, qh = tid >> 7;   // global-load row, k-half

    const float* Xp = X + (size_t)(m0 + gr) * K + 8 * qh;
    const float* Wp = W + (size_t)(n0 + gr) * K + 8 * qh;

    float4 xr0 = *(const float4*)Xp, xr1 = *(const float4*)(Xp + 4);
    float4 wr0 = *(const float4*)Wp, wr1 = *(const float4*)(Wp + 4);
    const int kq = 8 * qh;
    Xs[0][kq+0][gr]=xr0.x; Xs[0][kq+1][gr]=xr0.y; Xs[0][kq+2][gr]=xr0.z; Xs[0][kq+3][gr]=xr0.w;
    Xs[0][kq+4][gr]=xr1.x; Xs[0][kq+5][gr]=xr1.y; Xs[0][kq+6][gr]=xr1.z; Xs[0][kq+7][gr]=xr1.w;
    Ws[0][kq+0][gr]=wr0.x; Ws[0][kq+1][gr]=wr0.y; Ws[0][kq+2][gr]=wr0.z; Ws[0][kq+3][gr]=wr0.w;
    Ws[0][kq+4][gr]=wr1.x; Ws[0][kq+5][gr]=wr1.y; Ws[0][kq+6][gr]=wr1.z; Ws[0][kq+7][gr]=wr1.w;
    __syncthreads();

    ull acc[8][4];
#pragma unroll
    for (int i = 0; i < 8; i++)
#pragma unroll
        for (int j = 0; j < 4; j++) acc[i][j] = 0ull;

    const int NIT = K / 16;
    for (int it = 0; it < NIT; ++it) {
        const int cur = it & 1;
        if (it + 1 < NIT) {
            const float* xp = Xp + (it + 1) * 16;
            const float* wp = Wp + (it + 1) * 16;
            xr0 = *(const float4*)xp; xr1 = *(const float4*)(xp + 4);
            wr0 = *(const float4*)wp; wr1 = *(const float4*)(wp + 4);
        }
#pragma unroll
        for (int k = 0; k < 16; ++k) {
            float4 xa = *(const float4*)&Xs[cur][k][ty * 4];
            float4 xb = *(const float4*)&Xs[cur][k][64 + ty * 4];
            float4 wa = *(const float4*)&Ws[cur][k][tx * 4];
            float4 wb = *(const float4*)&Ws[cur][k][64 + tx * 4];
            ull p0 = pk2(wa.x, wa.y), p1 = pk2(wa.z, wa.w);
            ull p2 = pk2(wb.x, wb.y), p3 = pk2(wb.z, wb.w);
            ull a;
            a = pk2(xa.x, xa.x);
            fma2(acc[0][0],a,p0); fma2(acc[0][1],a,p1); fma2(acc[0][2],a,p2); fma2(acc[0][3],a,p3);
            a = pk2(xa.y, xa.y);
            fma2(acc[1][0],a,p0); fma2(acc[1][1],a,p1); fma2(acc[1][2],a,p2); fma2(acc[1][3],a,p3);
            a = pk2(xa.z, xa.z);
            fma2(acc[2][0],a,p0); fma2(acc[2][1],a,p1); fma2(acc[2][2],a,p2); fma2(acc[2][3],a,p3);
            a = pk2(xa.w, xa.w);
            fma2(acc[3][0],a,p0); fma2(acc[3][1],a,p1); fma2(acc[3][2],a,p2); fma2(acc[3][3],a,p3);
            a = pk2(xb.x, xb.x);
            fma2(acc[4][0],a,p0); fma2(acc[4][1],a,p1); fma2(acc[4][2],a,p2); fma2(acc[4][3],a,p3);
            a = pk2(xb.y, xb.y);
            fma2(acc[5][0],a,p0); fma2(acc[5][1],a,p1); fma2(acc[5][2],a,p2); fma2(acc[5][3],a,p3);
            a = pk2(xb.z, xb.z);
            fma2(acc[6][0],a,p0); fma2(acc[6][1],a,p1); fma2(acc[6][2],a,p2); fma2(acc[6][3],a,p3);
            a = pk2(xb.w, xb.w);
            fma2(acc[7][0],a,p0); fma2(acc[7][1],a,p1); fma2(acc[7][2],a,p2); fma2(acc[7][3],a,p3);
        }
        if (it + 1 < NIT) {
            const int nxt = cur ^ 1;
            Xs[nxt][kq+0][gr]=xr0.x; Xs[nxt][kq+1][gr]=xr0.y; Xs[nxt][kq+2][gr]=xr0.z; Xs[nxt][kq+3][gr]=xr0.w;
            Xs[nxt][kq+4][gr]=xr1.x; Xs[nxt][kq+5][gr]=xr1.y; Xs[nxt][kq+6][gr]=xr1.z; Xs[nxt][kq+7][gr]=xr1.w;
            Ws[nxt][kq+0][gr]=wr0.x; Ws[nxt][kq+1][gr]=wr0.y; Ws[nxt][kq+2][gr]=wr0.z; Ws[nxt][kq+3][gr]=wr0.w;
            Ws[nxt][kq+4][gr]=wr1.x; Ws[nxt][kq+5][gr]=wr1.y; Ws[nxt][kq+6][gr]=wr1.z; Ws[nxt][kq+7][gr]=wr1.w;
        }
        __syncthreads();
    }

    const int na = n0 + tx * 4, nb = na + 64;
    float bsA[4], bsB[4];
#pragma unroll
    for (int j = 0; j < 4; j++) {
        bsA[j] = bi[na + j] + bh[na + j];
        bsB[j] = bi[nb + j] + bh[nb + j];
    }
    float* base = g_xg + (size_t)dir * M * GH;
#pragma unroll
    for (int i = 0; i < 8; ++i) {
        const int m = m0 + (i < 4 ? ty * 4 + i : 64 + ty * 4 + (i - 4));
        float* y = base + (size_t)m * GH;
        float4 v;
        unpk2(acc[i][0], v.x, v.y); unpk2(acc[i][1], v.z, v.w);
        v.x += bsA[0]; v.y += bsA[1]; v.z += bsA[2]; v.w += bsA[3];
        *(float4*)(y + na) = v;
        unpk2(acc[i][2], v.x, v.y); unpk2(acc[i][3], v.z, v.w);
        v.x += bsB[0]; v.y += bsB[1]; v.z += bsB[2]; v.w += bsB[3];
        *(float4*)(y + nb) = v;
    }
}

// ---------------- LSTM recurrence (R10, proven) -----------------------------
// 512 threads. Thread (q = tid>>2, kh = tid&3) computes partial dots over
// k in [32kh, 32kh+32) for ALL 4 gate rows {q, q+128, q+256, q+384}, 4
// batches. Quad shuffle reduce-scatter over kh leaves thread with gates
// 0..3 for (batch kh, unit q). One barrier/step; hs ping-pongs.
__global__ void __launch_bounds__(512, 1) lstm_rec(
    int layer,
    const float* __restrict__ Wf, const float* __restrict__ Wr)
{
    extern __shared__ float sm[];
    float* sW  = sm;                       // WWORDS
    float* hsA = sm + WWORDS;              // HSW words
    float* hsB = hsA + HSW;

    const int dir = blockIdx.y;
    const int b0  = blockIdx.x * NB;
    const float* Whh = dir ? Wr : Wf;
    float* hout = layer ? g_h1 : g_h0;
    const float* xg = g_xg + (size_t)dir * Bb * Tt * GH;
    const int tid = threadIdx.x;
    const int q = tid >> 2, kh = tid & 3;

    // cooperative weight load: 2048 chunks x 6 float4
    for (int i = tid; i < 2048 * 6; i += 512) {
        const int ch = i / 6, fq = i - ch * 6;
        const int r = ch >> 2, kq = ch & 3;
        float4 v = *(const float4*)(Whh + (size_t)r * Hh + kq * 32 + fq * 4);
        *(float4*)(sW + wchunk(ch) + fq * 4) = v;
    }
    for (int i = tid; i < 2 * HSW; i += 512) hsA[i] = 0.f;

    // register weights: rows g*128+q, cols [32kh+24, 32kh+32)
    float4 wra[4], wrb[4];
#pragma unroll
    for (int g = 0; g < 4; ++g) {
        const float* src = Whh + (size_t)(g * Hh + q) * Hh + 32 * kh + 24;
        wra[g] = *(const float4*)src;
        wrb[g] = *(const float4*)(src + 4);
    }

    const float* wp = sW + wchunk(4 * q + kh);   // g offsets: +14080*g words
    const int hb = 136 * kh;
    const int mypair = kh >> 1, mybit = kh & 1;
    float c0 = 0.f;
    float* hp = hout + (size_t)(b0 + kh) * Tt * (2 * Hh) + dir * Hh + q;
    const float* xrow = xg + (size_t)(b0 + kh) * Tt * GH + q;
    __syncthreads();

    for (int s = 0; s < Tt; ++s) {
        const int t = dir ? (Tt - 1 - s) : s;
        const float* hcur = (s & 1) ? hsB : hsA;
        float* hnxt       = (s & 1) ? hsA : hsB;
        const float* xt = xrow + (size_t)t * GH;
        float xq0 = xt[0], xq1 = xt[128], xq2 = xt[256], xq3 = xt[384];

        ull A01[4] = {0, 0, 0, 0}, A23[4] = {0, 0, 0, 0};
        const float* hq = hcur + hb;
#pragma unroll
        for (int jf = 0; jf < 6; ++jf) {
            float4 w0 = *(const float4*)(wp + jf * 4);
            float4 w1 = *(const float4*)(wp + 14080 + jf * 4);
            float4 w2 = *(const float4*)(wp + 28160 + jf * 4);
            float4 w3 = *(const float4*)(wp + 42240 + jf * 4);
#pragma unroll
            for (int kk = 0; kk < 4; ++kk) {
                float4 hv = *(const float4*)(hq + (jf * 4 + kk) * 4);
                ull h01 = pk2(hv.x, hv.y), h23 = pk2(hv.z, hv.w);
                ull m0 = pk2(f4c(w0, kk), f4c(w0, kk));
                ull m1 = pk2(f4c(w1, kk), f4c(w1, kk));
                ull m2 = pk2(f4c(w2, kk), f4c(w2, kk));
                ull m3 = pk2(f4c(w3, kk), f4c(w3, kk));
                fma2(A01[0], m0, h01); fma2(A23[0], m0, h23);
                fma2(A01[1], m1, h01); fma2(A23[1], m1, h23);
                fma2(A01[2], m2, h01); fma2(A23[2], m2, h23);
                fma2(A01[3], m3, h01); fma2(A23[3], m3, h23);
            }
        }
#pragma unroll
        for (int jr = 0; jr < 8; ++jr) {
            float4 hv = *(const float4*)(hq + (24 + jr) * 4);
            ull h01 = pk2(hv.x, hv.y), h23 = pk2(hv.z, hv.w);
            float f0 = jr < 4 ? f4c(wra[0], jr) : f4c(wrb[0], jr - 4);
            float f1 = jr < 4 ? f4c(wra[1], jr) : f4c(wrb[1], jr - 4);
            float f2 = jr < 4 ? f4c(wra[2], jr) : f4c(wrb[2], jr - 4);
            float f3 = jr < 4 ? f4c(wra[3], jr) : f4c(wrb[3], jr - 4);
            ull m0 = pk2(f0, f0), m1 = pk2(f1, f1), m2 = pk2(f2, f2), m3 = pk2(f3, f3);
            fma2(A01[0], m0, h01); fma2(A23[0], m0, h23);
            fma2(A01[1], m1, h01); fma2(A23[1], m1, h23);
            fma2(A01[2], m2, h01); fma2(A23[2], m2, h23);
            fma2(A01[3], m3, h01); fma2(A23[3], m3, h23);
        }

        // quad reduce-scatter over kh: end with gates 0..3 for batch kh
        ull R[4];
#pragma unroll
        for (int g = 0; g < 4; ++g) {
            ull snd  = mypair ? A01[g] : A23[g];
            ull keep = mypair ? A23[g] : A01[g];
            ull rcv = __shfl_xor_sync(0xffffffffu, snd, 2);
            R[g] = add2(keep, rcv);
        }
#pragma unroll
        for (int g = 0; g < 4; ++g) {
            ull rcv = __shfl_xor_sync(0xffffffffu, R[g], 1);
            R[g] = add2(R[g], rcv);
        }
        float G0, G1, G2, G3;
        {
            float lo, hi;
            unpk2(R[0], lo, hi); G0 = mybit ? hi : lo;
            unpk2(R[1], lo, hi); G1 = mybit ? hi : lo;
            unpk2(R[2], lo, hi); G2 = mybit ? hi : lo;
            unpk2(R[3], lo, hi); G3 = mybit ? hi : lo;
        }
        G0 += xq0; G1 += xq1; G2 += xq2; G3 += xq3;

        // elementwise: (batch kh, unit q)
        c0 = sigf(G1) * c0 + sigf(G0) * tanhfast(G2);
        float h = sigf(G3) * tanhfast(c0);
        hnxt[4 * q + 8 * (q >> 5) + kh] = h;
        if (layer == 0 || t == Tt - 1)          // layer1: only t=T-1 consumed
            hp[(size_t)t * (2 * Hh)] = h;
        __syncthreads();
    }
}

// ---------------- FC head: out[b] = relu(last@fc1^T+b1) @ fc2^T + b2 -------
__global__ void __launch_bounds__(128) fc_head(
    const float* __restrict__ fc1w, const float* __restrict__ fc1b,
    const float* __restrict__ fc2w, const float* __restrict__ fc2b,
    float* __restrict__ out)
{
    __shared__ float last[2 * Hh];
    __shared__ float red[Hh];
    const int b = blockIdx.x, tid = threadIdx.x;
    const float* src = g_h1 + ((size_t)b * Tt + (Tt - 1)) * (2 * Hh);
    last[tid] = src[tid];
    last[tid + Hh] = src[tid + Hh];
    __syncthreads();
    float s = fc1b[tid];
    const float* wr = fc1w + tid * (2 * Hh);
#pragma unroll 8
    for (int k = 0; k < 2 * Hh; ++k) s += wr[k] * last[k];
    red[tid] = fmaxf(s, 0.f) * fc2w[tid];
    __syncthreads();
    for (int st = 64; st > 0; st >>= 1) {
        if (tid < st) red[tid] += red[tid + st];
        __syncthreads();
    }
    if (tid == 0) out[b] = red[0] + fc2b[0];
}

// ---------------- launch ---------------------------------------------------
extern "C" void kernel_launch(void* const* d_in, const int* in_sizes, int n_in,
                              void* d_out, int out_size)
{
    (void)in_sizes; (void)n_in; (void)out_size;
    const float* x     = (const float*)d_in[0];
    const float* Wih0  = (const float*)d_in[1];
    const float* Whh0  = (const float*)d_in[2];
    const float* bih0  = (const float*)d_in[3];
    const float* bhh0  = (const float*)d_in[4];
    const float* Wih0r = (const float*)d_in[5];
    const float* Whh0r = (const float*)d_in[6];
    const float* bih0r = (const float*)d_in[7];
    const float* bhh0r = (const float*)d_in[8];
    const float* Wih1  = (const float*)d_in[9];
    const float* Whh1  = (const float*)d_in[10];
    const float* bih1  = (const float*)d_in[11];
    const float* bhh1  = (const float*)d_in[12];
    const float* Wih1r = (const float*)d_in[13];
    const float* Whh1r = (const float*)d_in[14];
    const float* bih1r = (const float*)d_in[15];
    const float* bhh1r = (const float*)d_in[16];
    const float* fc1w  = (const float*)d_in[17];
    const float* fc1b  = (const float*)d_in[18];
    const float* fc2w  = (const float*)d_in[19];
    const float* fc2b  = (const float*)d_in[20];
    float* out = (float*)d_out;

    const int SMEMR = (WWORDS + 2 * HSW) * 4;   // 229,632 B <= 232,448 cap
    cudaFuncSetAttribute(lstm_rec, cudaFuncAttributeMaxDynamicSharedMemorySize, SMEMR);

    dim3 gg(Bb * Tt / 128, GH / 128, 2);
    dim3 gr(Bb / NB, 2);

    // layer 0
    xg_gemm<<<gg, 256>>>(x, 0, Ii, Wih0, Wih0r, bih0, bhh0, bih0r, bhh0r);
    lstm_rec<<<gr, 512, SMEMR>>>(0, Whh0, Whh0r);
    // layer 1 (input = g_h0, K = 256)
    xg_gemm<<<gg, 256>>>(x, 1, 2 * Hh, Wih1, Wih1r, bih1, bhh1, bih1r, bhh1r);
    lstm_rec<<<gr, 512, SMEMR>>>(1, Whh1, Whh1r);
    // head
    fc_head<<<Bb, Hh>>>(fc1w, fc1b, fc2w, fc2b, out);
}